// round 11
// baseline (speedup 1.0000x reference)
#include <cuda_runtime.h>
#include <cuda_bf16.h>
#include <cstdint>

// Problem constants: V voxels, 40 labels (1..40), fp32 one-hot output.
static constexpr int X = 256, Y = 256, Z = 48;
static constexpr int V = X * Y * Z;          // 3,145,728 voxels
static constexpr int NLAB = 40;              // channels
static constexpr int V4 = V / 4;             // 786,432 float4 groups per channel plane
static constexpr int GROUPS_PER_THREAD = 4;  // 4 x float4 = 16 voxels per thread
static constexpr int THREADS = 256;
static constexpr int NBLOCKS = V4 / (THREADS * GROUPS_PER_THREAD); // 768 -> one wave

__global__ __launch_bounds__(THREADS)
void onehot_kernel(const float* __restrict__ mask, float* __restrict__ out) {
    // Each thread owns 4 float4 groups strided by blockDim so each of the
    // 4 stores per plane iteration is a fully-coalesced 512B warp store.
    const size_t base = (size_t)blockIdx.x * (THREADS * GROUPS_PER_THREAD) + threadIdx.x;

    int lab[GROUPS_PER_THREAD][4];
    #pragma unroll
    for (int g = 0; g < GROUPS_PER_THREAD; ++g) {
        const float4 m = __ldg(reinterpret_cast<const float4*>(mask) + base + (size_t)g * THREADS);
        lab[g][0] = (int)m.x;
        lab[g][1] = (int)m.y;
        lab[g][2] = (int)m.z;
        lab[g][3] = (int)m.w;
    }

    float4* o = reinterpret_cast<float4*>(out) + base;
    #pragma unroll
    for (int c = 1; c <= NLAB; ++c) {
        #pragma unroll
        for (int g = 0; g < GROUPS_PER_THREAD; ++g) {
            float4 r;
            r.x = (lab[g][0] == c) ? 1.0f : 0.0f;
            r.y = (lab[g][1] == c) ? 1.0f : 0.0f;
            r.z = (lab[g][2] == c) ? 1.0f : 0.0f;
            r.w = (lab[g][3] == c) ? 1.0f : 0.0f;
            // Streaming store: 503 MB output, zero reuse — evict-first.
            __stcs(o + (size_t)g * THREADS, r);
        }
        o += (size_t)V4;   // next channel plane
    }
}

extern "C" void kernel_launch(void* const* d_in, const int* in_sizes, int n_in,
                              void* d_out, int out_size) {
    const float* mask = (const float*)d_in[0];
    float* out = (float*)d_out;
    onehot_kernel<<<NBLOCKS, THREADS>>>(mask, out);  // 768 blocks = single wave
}